// round 14
// baseline (speedup 1.0000x reference)
#include <cuda_runtime.h>
#include <cstdint>

// Batched outer product: out[i, j*K + l] = x[i,j] * y[i,l]
// n=4096, m=256, k=256 → out row = 65536 f32 = 16384 float4.
// Pure store-bandwidth kernel (~1.07 GB written) at the HBM write wall.
// R12: block=1024, 2 rows per CTA (grid=2048). Single prologue loads both
// rows' inputs (x→smem, y→regs), one barrier, then 32 uninterrupted
// float4 .cs store iterations. Continues the ramp-amortization trend.

static constexpr int M = 256;   // x row length
static constexpr int K = 256;   // y row length
static constexpr int ROW_F4 = (M * K) / 4;  // 16384 float4 per output row
static constexpr int BLK = 1024;

__global__ __launch_bounds__(BLK, 2)
void omul_kernel(const float* __restrict__ x,
                 const float* __restrict__ y,
                 float4* __restrict__ out)
{
    __shared__ float xs[2 * M];

    const int row0 = blockIdx.x * 2;
    const int t    = threadIdx.x;

    // Prologue: both rows' x into smem (threads 0..511), both rows' y
    // chunks into registers. y float4 index is (t & 63) for all iterations.
    if (t < 2 * M) xs[t] = x[(size_t)row0 * M + t];
    const float4* y4 = reinterpret_cast<const float4*>(y);
    const float4 yv0 = y4[(size_t)row0 * (K / 4) + (t & 63)];
    const float4 yv1 = y4[(size_t)(row0 + 1) * (K / 4) + (t & 63)];
    __syncthreads();

    float4* o = out + (size_t)row0 * ROW_F4;

    // Row 0: 16 iterations × 1024 threads = 16384 float4 stores.
    #pragma unroll
    for (int i = 0; i < 16; i++) {
        const int idx = i * BLK + t;
        const float xv = xs[idx >> 6];
        float4 r;
        r.x = xv * yv0.x;
        r.y = xv * yv0.y;
        r.z = xv * yv0.z;
        r.w = xv * yv0.w;
        __stcs(&o[idx], r);
    }
    // Row 1: next 16384 float4, x from second half of smem.
    #pragma unroll
    for (int i = 0; i < 16; i++) {
        const int idx = i * BLK + t;
        const float xv = xs[M + (idx >> 6)];
        float4 r;
        r.x = xv * yv1.x;
        r.y = xv * yv1.y;
        r.z = xv * yv1.z;
        r.w = xv * yv1.w;
        __stcs(&o[ROW_F4 + idx], r);
    }
}

extern "C" void kernel_launch(void* const* d_in, const int* in_sizes, int n_in,
                              void* d_out, int out_size)
{
    const float* x = (const float*)d_in[0];
    const float* y = (const float*)d_in[1];
    float4* out = (float4*)d_out;

    const int n = in_sizes[0] / M;  // 4096 rows
    omul_kernel<<<n / 2, BLK>>>(x, y, out);
}